// round 1
// baseline (speedup 1.0000x reference)
#include <cuda_runtime.h>

#define N 8192
#define F 128
#define ALPHA 0.2f
#define NEG_INF -9000000000000000.0f

// Allocation-free scratch
__device__ float g_Wa1[F];
__device__ float g_Wa2[F];
__device__ float g_si[N];
__device__ float g_sj[N];

// Kernel 0: Wa1 = W @ a[:F], Wa2 = W @ a[F:]   (128x128 matvec, one block)
__global__ void compute_Wa_kernel(const float* __restrict__ W,
                                  const float* __restrict__ a) {
    int k = threadIdx.x;  // 0..127  (row of W)
    float s1 = 0.f, s2 = 0.f;
    const float* wrow = W + k * F;
#pragma unroll 8
    for (int f = 0; f < F; ++f) {
        float w = wrow[f];
        s1 = fmaf(w, a[f], s1);
        s2 = fmaf(w, a[F + f], s2);
    }
    g_Wa1[k] = s1;
    g_Wa2[k] = s2;
}

// Kernel 1: s_i[r] = dot(v_i[r,:], Wa1), s_j[r] = dot(v_j[r,:], Wa2)
// One warp per row; lane handles 4 contiguous floats.
__global__ void compute_s_kernel(const float* __restrict__ vi,
                                 const float* __restrict__ vj) {
    int warp = (blockIdx.x * blockDim.x + threadIdx.x) >> 5;
    int lane = threadIdx.x & 31;
    if (warp >= N) return;

    float4 a1 = reinterpret_cast<const float4*>(g_Wa1)[lane];
    float4 a2 = reinterpret_cast<const float4*>(g_Wa2)[lane];
    float4 x1 = reinterpret_cast<const float4*>(vi + (size_t)warp * F)[lane];
    float4 x2 = reinterpret_cast<const float4*>(vj + (size_t)warp * F)[lane];

    float s1 = fmaf(x1.x, a1.x, fmaf(x1.y, a1.y, fmaf(x1.z, a1.z, x1.w * a1.w)));
    float s2 = fmaf(x2.x, a2.x, fmaf(x2.y, a2.y, fmaf(x2.z, a2.z, x2.w * a2.w)));

#pragma unroll
    for (int o = 16; o > 0; o >>= 1) {
        s1 += __shfl_down_sync(0xffffffffu, s1, o);
        s2 += __shfl_down_sync(0xffffffffu, s2, o);
    }
    if (lane == 0) {
        g_si[warp] = s1;
        g_sj[warp] = s2;
    }
}

// Kernel 2: per-row masked leaky-relu + softmax. One block per row.
// adj read once (int4), e staged in 32KB shared, output written once (float4).
__global__ __launch_bounds__(256) void softmax_row_kernel(
    const int* __restrict__ adj, float* __restrict__ out) {
    __shared__ float e_sh[N];
    __shared__ float red[32];
    __shared__ float bcast;

    const int row = blockIdx.x;
    const int tid = threadIdx.x;
    const int lane = tid & 31;
    const int wid = tid >> 5;

    const float si = g_si[row];
    const int4* adj4 = reinterpret_cast<const int4*>(adj + (size_t)row * N);
    const float4* sj4 = reinterpret_cast<const float4*>(g_sj);
    float4* esh4 = reinterpret_cast<float4*>(e_sh);
    float4* out4 = reinterpret_cast<float4*>(out + (size_t)row * N);

    // Pass 1: masked leaky-relu into shared, local max
    float lmax = NEG_INF;
#pragma unroll
    for (int j = tid; j < N / 4; j += 256) {
        int4 av = adj4[j];
        float4 sj = sj4[j];
        float4 e;
        float t;
        t = si + sj.x; t = t > 0.f ? t : ALPHA * t; e.x = av.x > 0 ? t : NEG_INF;
        t = si + sj.y; t = t > 0.f ? t : ALPHA * t; e.y = av.y > 0 ? t : NEG_INF;
        t = si + sj.z; t = t > 0.f ? t : ALPHA * t; e.z = av.z > 0 ? t : NEG_INF;
        t = si + sj.w; t = t > 0.f ? t : ALPHA * t; e.w = av.w > 0 ? t : NEG_INF;
        esh4[j] = e;
        lmax = fmaxf(lmax, fmaxf(fmaxf(e.x, e.y), fmaxf(e.z, e.w)));
    }
    // block max reduce
#pragma unroll
    for (int o = 16; o > 0; o >>= 1)
        lmax = fmaxf(lmax, __shfl_xor_sync(0xffffffffu, lmax, o));
    if (lane == 0) red[wid] = lmax;
    __syncthreads();
    if (wid == 0) {
        float m = red[lane & 7];
#pragma unroll
        for (int o = 4; o > 0; o >>= 1)
            m = fmaxf(m, __shfl_xor_sync(0xffffffffu, m, o));
        if (lane == 0) bcast = m;
    }
    __syncthreads();
    const float rmax = bcast;

    // Pass 2: exp(e - max) back into shared, local sum
    float lsum = 0.f;
#pragma unroll
    for (int j = tid; j < N / 4; j += 256) {
        float4 e = esh4[j];
        e.x = __expf(e.x - rmax);
        e.y = __expf(e.y - rmax);
        e.z = __expf(e.z - rmax);
        e.w = __expf(e.w - rmax);
        esh4[j] = e;
        lsum += (e.x + e.y) + (e.z + e.w);
    }
#pragma unroll
    for (int o = 16; o > 0; o >>= 1)
        lsum += __shfl_xor_sync(0xffffffffu, lsum, o);
    if (lane == 0) red[wid] = lsum;
    __syncthreads();
    if (wid == 0) {
        float s = red[lane & 7];
#pragma unroll
        for (int o = 4; o > 0; o >>= 1)
            s += __shfl_xor_sync(0xffffffffu, s, o);
        if (lane == 0) bcast = 1.0f / s;
    }
    __syncthreads();
    const float inv = bcast;

    // Pass 3: scaled write
#pragma unroll
    for (int j = tid; j < N / 4; j += 256) {
        float4 e = esh4[j];
        e.x *= inv; e.y *= inv; e.z *= inv; e.w *= inv;
        out4[j] = e;
    }
}

extern "C" void kernel_launch(void* const* d_in, const int* in_sizes, int n_in,
                              void* d_out, int out_size) {
    const float* v_i = (const float*)d_in[0];
    const float* v_j = (const float*)d_in[1];
    const int*   adj = (const int*)d_in[2];
    const float* W   = (const float*)d_in[3];
    const float* a   = (const float*)d_in[4];
    float* out = (float*)d_out;

    compute_Wa_kernel<<<1, F>>>(W, a);
    // 8 warps per block -> 8 rows per block -> N/8 = 1024 blocks
    compute_s_kernel<<<N / 8, 256>>>(v_i, v_j);
    softmax_row_kernel<<<N, 256>>>(adj, out);
}